// round 6
// baseline (speedup 1.0000x reference)
#include <cuda_runtime.h>

// out shape (256, 2, 512, 512) fp32.
// out[b,t,p,q] = sum_k vert[p,k]*hor[q,k]   (normalization by 1/PIXEL_AREA is
// folded in by scaling each factor by s = 1/SIDE = 1024/pi; PIXEL_AREA = SIDE^2).
//
// t==0 (hilbert):  K=64, x = s*{a0, b1}-{0,512}, y = s*{b0, a1}
//   hor[q,k]  = clamp(min((q+1) - x, y - q), 0, 1)
//   vert[p,k] = clamp(min((512-p) - y, x + (p+1)), 0, 1)
// t==1 (rank-inv): K=32, x = s*a0, y = s*b0
//   hor[q,k]  = clamp((q+1) - x, 0, 1)
//   vert[p,k] = clamp(y - (511-p), 0, 1)

#define TILE 128
#define KCHUNK 32
#define NTHREADS 256

typedef unsigned long long u64;

__device__ __forceinline__ float clamp01(float v) {
    return fminf(fmaxf(v, 0.0f), 1.0f);
}

// packed 2xfp32 FMA: d = a*b + d  (ptxas will not emit FFMA2 from C++)
__device__ __forceinline__ void fma2(u64& d, u64 a, u64 b) {
    asm("fma.rn.f32x2 %0, %1, %2, %0;" : "+l"(d) : "l"(a), "l"(b));
}

__device__ __forceinline__ u64 bcast2(float v) {
    u64 r;
    unsigned u = __float_as_uint(v);
    asm("mov.b64 %0, {%1, %1};" : "=l"(r) : "r"(u));
    return r;
}

__global__ __launch_bounds__(NTHREADS, 2)
void raster_kernel(const float* __restrict__ in00,
                   const float* __restrict__ in01,
                   float* __restrict__ out)
{
    const int qTile = blockIdx.x * TILE;
    const int pTile = blockIdx.y * TILE;
    const int z = blockIdx.z;          // b*2 + t
    const int b = z >> 1;
    const int t = z & 1;
    const int K = t ? 32 : 64;
    const float S = 325.94932345220164f;  // 1024/pi

    __shared__ float vert_s[KCHUNK][TILE];
    __shared__ float hor_s[KCHUNK][TILE];
    __shared__ float sx[64];
    __shared__ float sy[64];

    const int tid = threadIdx.x;

    // Stage scaled interval endpoints for this (b, t).
    if (tid < K) {
        float x, y;
        if (t == 0) {
            if (tid < 32) {
                x = S * in00[b * 64 + 2 * tid];      // a0
                y = S * in00[b * 64 + 2 * tid + 1];  // b0
            } else {
                int j = tid - 32;
                x = S * in01[b * 64 + 2 * j + 1] - 512.0f;  // b1 - STRIP (scaled)
                y = S * in01[b * 64 + 2 * j];               // a1
            }
        } else {
            x = S * in00[b * 64 + 2 * tid];      // a0
            y = S * in00[b * 64 + 2 * tid + 1];  // b0
        }
        sx[tid] = x;
        sy[tid] = y;
    }
    __syncthreads();

    const int tx = tid & 15;   // q microtile index
    const int ty = tid >> 4;   // p microtile index

    // acc2[i][j] packs out columns (2j, 2j+1) for row i of the 8x8 microtile.
    u64 acc2[8][4];
    #pragma unroll
    for (int i = 0; i < 8; i++)
        #pragma unroll
        for (int j = 0; j < 4; j++)
            acc2[i][j] = 0ull;

    for (int kc = 0; kc < K; kc += KCHUNK) {
        // Fill vert/hor tiles for this K chunk (each thread does 16 elems).
        for (int i = tid; i < KCHUNK * TILE; i += NTHREADS) {
            int kl = i >> 7;          // local k (0..31)
            int pq = i & 127;         // local p / q within tile
            int kg = kc + kl;
            float x = sx[kg];
            float y = sy[kg];
            int q = qTile + pq;
            int p = pTile + pq;
            float h, v;
            if (t == 0) {
                h = clamp01(fminf((float)(q + 1) - x, y - (float)q));
                v = clamp01(fminf((float)(512 - p) - y, x + (float)(p + 1)));
            } else {
                h = clamp01((float)(q + 1) - x);
                v = clamp01(y - (float)(511 - p));
            }
            hor_s[kl][pq] = h;
            vert_s[kl][pq] = v;
        }
        __syncthreads();

        // 8x8 register-blocked accumulation, packed 2-wide along q.
        #pragma unroll 4
        for (int k = 0; k < KCHUNK; k++) {
            float4 v0 = *(const float4*)&vert_s[k][ty * 8];
            float4 v1 = *(const float4*)&vert_s[k][ty * 8 + 4];
            // hor pairs load directly as 64-bit packed operands (32B-aligned).
            const u64* hpp = (const u64*)&hor_s[k][tx * 8];
            u64 hp[4];
            #pragma unroll
            for (int j = 0; j < 4; j++) hp[j] = hpp[j];

            u64 vb[8];
            vb[0] = bcast2(v0.x); vb[1] = bcast2(v0.y);
            vb[2] = bcast2(v0.z); vb[3] = bcast2(v0.w);
            vb[4] = bcast2(v1.x); vb[5] = bcast2(v1.y);
            vb[6] = bcast2(v1.z); vb[7] = bcast2(v1.w);

            #pragma unroll
            for (int i = 0; i < 8; i++)
                #pragma unroll
                for (int j = 0; j < 4; j++)
                    fma2(acc2[i][j], vb[i], hp[j]);
        }
        __syncthreads();
    }

    // Write 8x8 microtile: rows p = pTile + ty*8 + i, cols q = qTile + tx*8 + j.
    float* o = out + (size_t)z * 262144 + (size_t)(pTile + ty * 8) * 512
                   + (qTile + tx * 8);
    #pragma unroll
    for (int i = 0; i < 8; i++) {
        float2 c0 = *(float2*)&acc2[i][0];
        float2 c1 = *(float2*)&acc2[i][1];
        float2 c2 = *(float2*)&acc2[i][2];
        float2 c3 = *(float2*)&acc2[i][3];
        float4 w0 = make_float4(c0.x, c0.y, c1.x, c1.y);
        float4 w1 = make_float4(c2.x, c2.y, c3.x, c3.y);
        *(float4*)(o + (size_t)i * 512) = w0;
        *(float4*)(o + (size_t)i * 512 + 4) = w1;
    }
}

extern "C" void kernel_launch(void* const* d_in, const int* in_sizes, int n_in,
                              void* d_out, int out_size)
{
    const float* in00 = (const float*)d_in[0];  // intervals00 (256,32,2)
    const float* in01 = (const float*)d_in[1];  // intervals01 (256,32,2)
    float* out = (float*)d_out;                 // (256,2,512,512)

    dim3 grid(512 / TILE, 512 / TILE, 512);     // (4, 4, 256*2)
    raster_kernel<<<grid, NTHREADS>>>(in00, in01, out);
}

// round 16
// speedup vs baseline: 1.8909x; 1.8909x over previous
#include <cuda_runtime.h>
#include <cuda_bf16.h>
#include <cstdint>

// out shape (256, 2, 512, 512) fp32.
// out[b,t,p,q] = sum_k vert[p,k]*hor[q,k]; factors pre-scaled by s=1/SIDE=1024/pi
// (absorbs /PIXEL_AREA exactly). fp32 factors split hi/lo into bf16;
// D = Ah*Bh + Ah*Bl + Al*Bh via mma.sync bf16 (fp32 accum); dropped Al*Bl ~1e-5.
//
// CTA: 128(p) x 128(q), 8 warps as 4(m) x 2(n), warp tile 32x64.
// SMEM tiles: vert/hor hi/lo, [128 rows][K cols bf16], row stride 144 B
// (72 bf16) so ldmatrix rows hit distinct 16B bank groups (16*r mod 128).

#define NTHREADS 256

#define TSTRIDE 144                    // bytes per tile row
#define TILE_BYTES (128 * TSTRIDE)     // 18432
#define SM_SX   0
#define SM_SY   256
#define SM_A_HI 512
#define SM_A_LO (SM_A_HI + TILE_BYTES)
#define SM_B_HI (SM_A_LO + TILE_BYTES)
#define SM_B_LO (SM_B_HI + TILE_BYTES)
#define SMEM_TOTAL (SM_B_LO + TILE_BYTES)   // 74240 B

__device__ __forceinline__ float clamp01(float v) {
    return fminf(fmaxf(v, 0.0f), 1.0f);
}

__device__ __forceinline__ uint32_t smem_u32(const void* p) {
    uint32_t a;
    asm("{ .reg .u64 t; cvta.to.shared.u64 t, %1; cvt.u32.u64 %0, t; }"
        : "=r"(a) : "l"(p));
    return a;
}

// split v0,v1 into bf16 hi pair (v0 in low half) + bf16 lo residual pair
__device__ __forceinline__ void split2(float v0, float v1, uint32_t& h2, uint32_t& l2) {
    asm("cvt.rn.bf16x2.f32 %0, %1, %2;" : "=r"(h2) : "f"(v1), "f"(v0));
    float h0f = __uint_as_float(h2 << 16);
    float h1f = __uint_as_float(h2 & 0xFFFF0000u);
    float l0 = v0 - h0f;
    float l1 = v1 - h1f;
    asm("cvt.rn.bf16x2.f32 %0, %1, %2;" : "=r"(l2) : "f"(l1), "f"(l0));
}

__device__ __forceinline__ void ldmx4(uint32_t* r, uint32_t addr) {
    asm volatile(
        "ldmatrix.sync.aligned.m8n8.x4.shared.b16 {%0,%1,%2,%3}, [%4];"
        : "=r"(r[0]), "=r"(r[1]), "=r"(r[2]), "=r"(r[3]) : "r"(addr));
}

__device__ __forceinline__ void mma_bf16(float* d, const uint32_t* a,
                                         uint32_t b0, uint32_t b1) {
    asm volatile(
        "mma.sync.aligned.m16n8k16.row.col.f32.bf16.bf16.f32 "
        "{%0,%1,%2,%3}, {%4,%5,%6,%7}, {%8,%9}, {%0,%1,%2,%3};"
        : "+f"(d[0]), "+f"(d[1]), "+f"(d[2]), "+f"(d[3])
        : "r"(a[0]), "r"(a[1]), "r"(a[2]), "r"(a[3]), "r"(b0), "r"(b1));
}

__global__ __launch_bounds__(NTHREADS, 2)
void raster_hmma(const float* __restrict__ in00,
                 const float* __restrict__ in01,
                 float* __restrict__ out)
{
    extern __shared__ char smem[];
    const uint32_t smem_base = smem_u32(smem);
    const int tid = threadIdx.x;
    const int lane = tid & 31;
    const int wid = tid >> 5;

    const int qTile = blockIdx.x * 128;
    const int pTile = blockIdx.y * 128;
    const int z = blockIdx.z;          // b*2 + t
    const int b = z >> 1;
    const int t = z & 1;
    const int K = t ? 32 : 64;
    const float S = 325.94932345220164f;  // 1024/pi

    float* sxs = (float*)(smem + SM_SX);
    float* sys = (float*)(smem + SM_SY);
    if (tid < K) {
        float x, y;
        if (t == 0) {
            if (tid < 32) {
                x = S * in00[b * 64 + 2 * tid];             // s*a0
                y = S * in00[b * 64 + 2 * tid + 1];         // s*b0
            } else {
                int j = tid - 32;
                x = S * in01[b * 64 + 2 * j + 1] - 512.0f;  // s*b1 - 512
                y = S * in01[b * 64 + 2 * j];               // s*a1
            }
        } else {
            x = S * in00[b * 64 + 2 * tid];
            y = S * in00[b * 64 + 2 * tid + 1];
        }
        sxs[tid] = x;
        sys[tid] = y;
    }
    __syncthreads();

    // ---- Fill factor tiles (bf16 hi/lo pairs, 2 k per u32 write) ----
    const int kpsh = t ? 4 : 5;            // log2(K/2)
    const int nkp = K >> 1;                // k-pairs per row
    const int ntile = 128 * nkp;           // tasks per A/B
    for (int idx = tid; idx < 2 * ntile; idx += NTHREADS) {
        int sel = (idx >= ntile);          // 0=A(vert,p), 1=B(hor,q)
        int rem = sel ? idx - ntile : idx;
        int row = rem >> kpsh;
        int kp = rem & (nkp - 1);
        int k0 = 2 * kp;
        float x0 = sxs[k0], y0 = sys[k0];
        float x1 = sxs[k0 + 1], y1 = sys[k0 + 1];
        float v0, v1;
        if (sel == 0) {
            int p = pTile + row;
            float f512p = (float)(512 - p), fp1 = (float)(p + 1);
            float f511p = (float)(511 - p);
            if (t == 0) {
                v0 = clamp01(fminf(f512p - y0, x0 + fp1));
                v1 = clamp01(fminf(f512p - y1, x1 + fp1));
            } else {
                v0 = clamp01(y0 - f511p);
                v1 = clamp01(y1 - f511p);
            }
        } else {
            int q = qTile + row;
            float fq1 = (float)(q + 1), fq = (float)q;
            if (t == 0) {
                v0 = clamp01(fminf(fq1 - x0, y0 - fq));
                v1 = clamp01(fminf(fq1 - x1, y1 - fq));
            } else {
                v0 = clamp01(fq1 - x0);
                v1 = clamp01(fq1 - x1);
            }
        }
        uint32_t h2, l2;
        split2(v0, v1, h2, l2);
        uint32_t off = row * TSTRIDE + kp * 4;
        int hbase = sel ? SM_B_HI : SM_A_HI;
        int lbase = sel ? SM_B_LO : SM_A_LO;
        *(uint32_t*)(smem + hbase + off) = h2;
        *(uint32_t*)(smem + lbase + off) = l2;
    }
    __syncthreads();

    // ---- Warp-tiled HMMA mainloop ----
    const int wm = wid & 3;                // warp row (m): 4 x 32
    const int wn = wid >> 2;               // warp col (n): 2 x 64

    // A ldmatrix x4 addr: lanes 0-7 rows m0-7 @k, 8-15 rows m8-15 @k,
    // 16-23 rows m0-7 @k+8, 24-31 rows m8-15 @k+8.
    uint32_t a_off = (uint32_t)(wm * 32 + (lane & 15)) * TSTRIDE
                   + (uint32_t)(lane >> 4) * 16;
    uint32_t aAh = smem_base + SM_A_HI + a_off;
    uint32_t aAl = smem_base + SM_A_LO + a_off;
    // B ldmatrix x4 addr: lanes 0-7 rows n0-7 @k, 8-15 rows n0-7 @k+8,
    // 16-23 rows n8-15 @k, 24-31 rows n8-15 @k+8.
    uint32_t b_off = (uint32_t)(wn * 64 + ((lane >> 4) << 3) + (lane & 7)) * TSTRIDE
                   + (uint32_t)((lane >> 3) & 1) * 16;
    uint32_t aBh = smem_base + SM_B_HI + b_off;
    uint32_t aBl = smem_base + SM_B_LO + b_off;

    float acc[2][8][4];
    #pragma unroll
    for (int mb = 0; mb < 2; mb++)
        #pragma unroll
        for (int nb = 0; nb < 8; nb++)
            #pragma unroll
            for (int r = 0; r < 4; r++)
                acc[mb][nb][r] = 0.0f;

    const int nks = K >> 4;                // 4 (hf) or 2 (ri)
    for (int ks = 0; ks < nks; ks++) {
        uint32_t kb = (uint32_t)ks * 32;   // 16 bf16 = 32 B
        uint32_t Ah[2][4], Al[2][4];
        ldmx4(Ah[0], aAh + kb);
        ldmx4(Ah[1], aAh + 16 * TSTRIDE + kb);
        ldmx4(Al[0], aAl + kb);
        ldmx4(Al[1], aAl + 16 * TSTRIDE + kb);
        #pragma unroll
        for (int nblk = 0; nblk < 4; nblk++) {
            uint32_t Bh[4], Bl[4];
            ldmx4(Bh, aBh + nblk * 16 * TSTRIDE + kb);
            ldmx4(Bl, aBl + nblk * 16 * TSTRIDE + kb);
            #pragma unroll
            for (int mb = 0; mb < 2; mb++) {
                float* d0 = acc[mb][2 * nblk + 0];
                float* d1 = acc[mb][2 * nblk + 1];
                mma_bf16(d0, Ah[mb], Bh[0], Bh[1]);
                mma_bf16(d0, Al[mb], Bh[0], Bh[1]);
                mma_bf16(d0, Ah[mb], Bl[0], Bl[1]);
                mma_bf16(d1, Ah[mb], Bh[2], Bh[3]);
                mma_bf16(d1, Al[mb], Bh[2], Bh[3]);
                mma_bf16(d1, Ah[mb], Bl[2], Bl[3]);
            }
        }
    }

    // ---- Epilogue: d0,d1 -> (row g, cols 2tig,2tig+1); d2,d3 -> row g+8 ----
    const int g = lane >> 2;
    const int tig = lane & 3;
    #pragma unroll
    for (int mb = 0; mb < 2; mb++) {
        int prow = pTile + wm * 32 + mb * 16 + g;
        float* o = out + (size_t)z * 262144 + (size_t)prow * 512
                 + (qTile + wn * 64 + 2 * tig);
        #pragma unroll
        for (int nb = 0; nb < 8; nb++) {
            __stcs((float2*)(o + nb * 8),
                   make_float2(acc[mb][nb][0], acc[mb][nb][1]));
            __stcs((float2*)(o + 8 * 512 + nb * 8),
                   make_float2(acc[mb][nb][2], acc[mb][nb][3]));
        }
    }
}

extern "C" void kernel_launch(void* const* d_in, const int* in_sizes, int n_in,
                              void* d_out, int out_size)
{
    const float* in00 = (const float*)d_in[0];  // intervals00 (256,32,2)
    const float* in01 = (const float*)d_in[1];  // intervals01 (256,32,2)
    float* out = (float*)d_out;                 // (256,2,512,512)

    cudaFuncSetAttribute(raster_hmma,
                         cudaFuncAttributeMaxDynamicSharedMemorySize, SMEM_TOTAL);
    dim3 grid(4, 4, 512);
    raster_hmma<<<grid, NTHREADS, SMEM_TOTAL>>>(in00, in01, out);
}